// round 1
// baseline (speedup 1.0000x reference)
#include <cuda_runtime.h>

#define TPB 256
#define STR 68   // padded row stride (floats) for all 64-wide smem tiles

// ---- packed f32x2 helpers (Blackwell FFMA2: only reachable via PTX) ----
__device__ __forceinline__ unsigned long long pk2(float lo, float hi){
    unsigned long long r;
    asm("mov.b64 %0, {%1,%2};" : "=l"(r) : "f"(lo), "f"(hi));
    return r;
}
__device__ __forceinline__ unsigned long long fma2(unsigned long long a,
                                                   unsigned long long b,
                                                   unsigned long long c){
    unsigned long long d;
    asm("fma.rn.f32x2 %0, %1, %2, %3;" : "=l"(d) : "l"(a), "l"(b), "l"(c));
    return d;
}
__device__ __forceinline__ float2 upk2(unsigned long long v){
    float2 f;
    asm("mov.b64 {%0,%1}, %2;" : "=f"(f.x), "=f"(f.y) : "l"(v));
    return f;
}

// shared memory float offsets
#define OFF_D 0
#define OFF_B 64
#define OFF_X 128
#define OFF_T (OFF_X + 64*STR)
#define OFF_C (OFF_T + 64*STR)
#define OFF_W (OFF_C + 64*STR)
#define SMEM_FLOATS (OFF_W + 3*64*STR)

extern "C" __global__ void __launch_bounds__(TPB, 2)
dct_conv_kernel(const float* __restrict__ x, const float* __restrict__ cw,
                const float* __restrict__ cb, float* __restrict__ out)
{
    extern __shared__ float sm[];
    float* sD = sm + OFF_D;   // 8x8 DCT matrix
    float* sB = sm + OFF_B;   // bias
    float* sX = sm + OFF_X;   // input blocks [ch][64] (reused as conv output Y)
    float* sT = sm + OFF_T;   // DCT temp (reused as conv reduction buffer)
    float* sC = sm + OFF_C;   // DCT coefs [i][t], cols 64..67 zero (reused as IDCT temp)
    float* sW = sm + OFF_W;   // weights [w][i][o], row stride 68

    const int tid = threadIdx.x;
    const int bid = blockIdx.x;
    const int b   = bid >> 10;
    const int pos = bid & 1023;
    const int bh  = pos >> 5;
    const int bw  = pos & 31;

    // ---- build D, load bias ----
    if (tid < 64){
        int k = tid >> 3, n = tid & 7;
        float v = 0.5f * cospif((float)((2*n+1)*k) * (1.0f/16.0f));
        if (k == 0) v *= 0.70710678118654752f;
        sD[tid] = v;
        sB[tid] = cb[tid];
    }
    // ---- stage W transposed: sW[w][i][o] ----
    for (int g = tid; g < 64*64*3; g += TPB){
        int o = g / 192;
        int r = g - o*192;
        int i = r / 3;
        int w = r - i*3;
        sW[(w*64 + i)*STR + o] = cw[g];
    }
    // ---- load x block for all channels ----
    const int ch = tid >> 2, q = tid & 3;
    {
        const float* gx = x + (((size_t)(b*64 + ch))*256 + (size_t)(bh*8))*256 + bw*8;
        #pragma unroll
        for (int rr = 0; rr < 2; rr++){
            int r = q*2 + rr;
            float4 v0 = *(const float4*)(gx + r*256);
            float4 v1 = *(const float4*)(gx + r*256 + 4);
            float* d = sX + ch*STR + r*8;
            *(float4*)(d)   = v0;
            *(float4*)(d+4) = v1;
        }
    }
    __syncthreads();

    // ---- forward DCT stage 1: T = D * X  (T[k][m] = sum_n D[k,n] X[n,m]) ----
    {
        float a0[8], a1[8];
        #pragma unroll
        for (int m=0;m<8;m++){ a0[m]=0.f; a1[m]=0.f; }
        const int k0 = q*2;
        #pragma unroll
        for (int n=0;n<8;n++){
            float4 x0 = *(const float4*)(sX + ch*STR + n*8);
            float4 x1 = *(const float4*)(sX + ch*STR + n*8 + 4);
            float xs[8] = {x0.x,x0.y,x0.z,x0.w,x1.x,x1.y,x1.z,x1.w};
            float d0 = sD[k0*8+n], d1 = sD[(k0+1)*8+n];
            #pragma unroll
            for (int m=0;m<8;m++){ a0[m] = fmaf(d0, xs[m], a0[m]);
                                   a1[m] = fmaf(d1, xs[m], a1[m]); }
        }
        float* tp = sT + ch*STR + k0*8;
        #pragma unroll
        for (int m=0;m<8;m++){ tp[m] = a0[m]; tp[8+m] = a1[m]; }
    }
    __syncthreads();

    // ---- forward DCT stage 2: C = T * D^T  (C[k][l] = sum_m T[k,m] D[l,m]) ----
    {
        #pragma unroll
        for (int kk=0;kk<2;kk++){
            int k = q*2+kk;
            float4 t0 = *(const float4*)(sT + ch*STR + k*8);
            float4 t1 = *(const float4*)(sT + ch*STR + k*8 + 4);
            float ts[8] = {t0.x,t0.y,t0.z,t0.w,t1.x,t1.y,t1.z,t1.w};
            float ov[8];
            #pragma unroll
            for (int l=0;l<8;l++){
                float s = 0.f;
                #pragma unroll
                for (int m=0;m<8;m++) s = fmaf(ts[m], sD[l*8+m], s);
                ov[l] = s;
            }
            float* cp = sC + ch*STR + k*8;
            #pragma unroll
            for (int l=0;l<8;l++) cp[l] = ov[l];
        }
        if (q == 0){
            float* cp = sC + ch*STR;
            cp[64]=0.f; cp[65]=0.f; cp[66]=0.f; cp[67]=0.f;
        }
    }
    __syncthreads();

    // ---- conv: Y[o][t] = bias[o] + sum_{i,w} W[o,i,w] * C[i][t+w] ----
    // thread tile: 4 o (as two f32x2 pairs) x 8 t, split i over two thread halves
    const int t3 = tid & 7;
    const int o4 = (tid >> 3) & 15;
    const int ih = tid >> 7;
    const int t0 = t3*8, o0 = o4*4;

    unsigned long long acc[2][8];
    #pragma unroll
    for (int p=0;p<2;p++)
        #pragma unroll
        for (int t=0;t<8;t++) acc[p][t] = 0ull;

    #pragma unroll 2
    for (int ii = 0; ii < 32; ii++){
        const int i = (ih << 5) + ii;
        const float* crow = sC + i*STR + t0;
        float4 c0 = *(const float4*)crow;
        float4 c1 = *(const float4*)(crow + 4);
        float c8 = crow[8], c9 = crow[9];
        unsigned long long cs[10];
        cs[0]=pk2(c0.x,c0.x); cs[1]=pk2(c0.y,c0.y); cs[2]=pk2(c0.z,c0.z); cs[3]=pk2(c0.w,c0.w);
        cs[4]=pk2(c1.x,c1.x); cs[5]=pk2(c1.y,c1.y); cs[6]=pk2(c1.z,c1.z); cs[7]=pk2(c1.w,c1.w);
        cs[8]=pk2(c8,c8);     cs[9]=pk2(c9,c9);
        #pragma unroll
        for (int w=0; w<3; w++){
            const float* wr = sW + (w*64 + i)*STR + o0;
            ulonglong2 wp = *(const ulonglong2*)wr;  // pairs (o0,o0+1),(o0+2,o0+3)
            #pragma unroll
            for (int tt=0; tt<8; tt++){
                acc[0][tt] = fma2(wp.x, cs[tt+w], acc[0][tt]);
                acc[1][tt] = fma2(wp.y, cs[tt+w], acc[1][tt]);
            }
        }
    }

    // ---- cross-half reduction + bias, write Y into sX ----
    unsigned long long* sRedU = (unsigned long long*)sT;  // sT free after F2
    if (ih){
        const int row = tid - 128;
        #pragma unroll
        for (int j=0;j<16;j++) sRedU[row*17 + j] = acc[j>>3][j&7];
    }
    __syncthreads();
    if (!ih){
        #pragma unroll
        for (int op=0; op<2; op++){
            const int oA = o0 + op*2, oB = oA + 1;
            const float bA = sB[oA], bB = sB[oB];
            #pragma unroll
            for (int tt=0; tt<8; tt++){
                float2 m = upk2(acc[op][tt]);
                float2 p = upk2(sRedU[tid*17 + op*8 + tt]);
                sX[oA*STR + t0 + tt] = m.x + p.x + bA;
                sX[oB*STR + t0 + tt] = m.y + p.y + bB;
            }
        }
    }
    __syncthreads();

    // ---- inverse stage 1: P = Y * D  (P[k][m] = sum_l Y[k,l] D[l,m]) ----
    {
        #pragma unroll
        for (int kk=0;kk<2;kk++){
            int k = q*2+kk;
            const float* yr = sX + ch*STR + k*8;
            float a[8];
            #pragma unroll
            for (int m=0;m<8;m++) a[m]=0.f;
            #pragma unroll
            for (int l=0;l<8;l++){
                float yv = yr[l];
                float4 d0 = *(const float4*)(sD + l*8);
                float4 d1 = *(const float4*)(sD + l*8 + 4);
                a[0]=fmaf(yv,d0.x,a[0]); a[1]=fmaf(yv,d0.y,a[1]);
                a[2]=fmaf(yv,d0.z,a[2]); a[3]=fmaf(yv,d0.w,a[3]);
                a[4]=fmaf(yv,d1.x,a[4]); a[5]=fmaf(yv,d1.y,a[5]);
                a[6]=fmaf(yv,d1.z,a[6]); a[7]=fmaf(yv,d1.w,a[7]);
            }
            float* pp = sC + ch*STR + k*8;
            #pragma unroll
            for (int m=0;m<8;m++) pp[m] = a[m];
        }
    }
    __syncthreads();

    // ---- inverse stage 2: img[n][m] = sum_k D[k,n] P[k][m]; store to gmem ----
    {
        float a0[8], a1[8];
        #pragma unroll
        for (int m=0;m<8;m++){ a0[m]=0.f; a1[m]=0.f; }
        const int n0 = q*2;
        #pragma unroll
        for (int k=0;k<8;k++){
            float4 p0 = *(const float4*)(sC + ch*STR + k*8);
            float4 p1 = *(const float4*)(sC + ch*STR + k*8 + 4);
            float ps[8] = {p0.x,p0.y,p0.z,p0.w,p1.x,p1.y,p1.z,p1.w};
            float d0 = sD[k*8 + n0], d1 = sD[k*8 + n0 + 1];
            #pragma unroll
            for (int m=0;m<8;m++){ a0[m] = fmaf(d0, ps[m], a0[m]);
                                   a1[m] = fmaf(d1, ps[m], a1[m]); }
        }
        float* go = out + (((size_t)(b*64 + ch))*256 + (size_t)(bh*8))*256 + bw*8;
        float4 w0 = make_float4(a0[0],a0[1],a0[2],a0[3]);
        float4 w1 = make_float4(a0[4],a0[5],a0[6],a0[7]);
        float4 w2 = make_float4(a1[0],a1[1],a1[2],a1[3]);
        float4 w3 = make_float4(a1[4],a1[5],a1[6],a1[7]);
        *(float4*)(go + n0*256)       = w0;
        *(float4*)(go + n0*256 + 4)   = w1;
        *(float4*)(go + (n0+1)*256)   = w2;
        *(float4*)(go + (n0+1)*256+4) = w3;
    }
}

extern "C" void kernel_launch(void* const* d_in, const int* in_sizes, int n_in,
                              void* d_out, int out_size)
{
    (void)in_sizes; (void)n_in; (void)out_size;
    const float* x  = (const float*)d_in[0];
    const float* cw = (const float*)d_in[1];
    const float* cb = (const float*)d_in[2];
    float* out = (float*)d_out;

    const size_t smem = (size_t)SMEM_FLOATS * sizeof(float);  // ~105 KB
    cudaFuncSetAttribute(dct_conv_kernel,
                         cudaFuncAttributeMaxDynamicSharedMemorySize, (int)smem);
    dct_conv_kernel<<<8192, TPB, smem>>>(x, cw, cb, out);
}